// round 7
// baseline (speedup 1.0000x reference)
#include <cuda_runtime.h>
#include <cstdint>

// Depth-to-space r=4, x-major channel ordering:
//   out[b, c, y, x] = in[b, c*16 + 4*(x%4) + (y%4), y/4, x/4]
// in : (16, 4096, 32, 32) fp32, out: (16, 256, 128, 128) fp32.
//
// Each (b,c) = contiguous 64KB in-block -> contiguous 64KB out-block.
// One CTA (512 thr) per block, smem-staged so BOTH HBM streams are dense:
//   warp w loads channel w (4KB) via 4x ld.v8 (1KB dense per instruction)
//   -> padded smem (per-channel +16B: conflict-free LDS.128 on permute)
//   -> __syncthreads -> register transpose -> dense v8 stores (4KB/warp).
// 3 CTAs/SM (65.8KB smem each) overlap load/store phases across CTAs.

#define CH_F4   257                     // 256 float4 + 1 pad per channel
#define SMEM_BYTES (16 * CH_F4 * 16)    // 65792

__global__ void __launch_bounds__(512) scale_transfer_stage_kernel(
    const float* __restrict__ in, float* __restrict__ out)
{
    extern __shared__ __align__(16) float4 s4[];

    const int tid = threadIdx.x;
    const size_t blk = blockIdx.x;                 // (b*256 + c)
    const float* src = in + blk * 16384;

    // ---- load phase: warp w <-> input channel w (4KB dense) ----
    {
        const int w = tid >> 5;
        const int l = tid & 31;
#pragma unroll
        for (int j = 0; j < 4; j++) {
            const float* q = src + w * 1024 + j * 256 + l * 8;
            float t0,t1,t2,t3,t4,t5,t6,t7;
            asm volatile(
                "ld.global.nc.v8.f32 {%0,%1,%2,%3,%4,%5,%6,%7}, [%8];"
                : "=f"(t0),"=f"(t1),"=f"(t2),"=f"(t3),
                  "=f"(t4),"=f"(t5),"=f"(t6),"=f"(t7)
                : "l"(q));
            unsigned a = w * CH_F4 + j * 64 + l * 2;
            s4[a]     = make_float4(t0, t1, t2, t3);
            s4[a + 1] = make_float4(t4, t5, t6, t7);
        }
    }
    __syncthreads();

    // ---- permute + store phase ----
    const unsigned xq = tid & 3;
    const unsigned y  = tid >> 2;       // 0..127
    const unsigned yr = y & 3;
    const unsigned yb = y >> 2;

    float r[4][8];
#pragma unroll
    for (int xr = 0; xr < 4; xr++) {
        unsigned ch = 4 * xr + yr;
        unsigned a = ch * CH_F4 + yb * 8 + xq * 2;
        float4 A = s4[a];
        float4 B = s4[a + 1];
        r[xr][0]=A.x; r[xr][1]=A.y; r[xr][2]=A.z; r[xr][3]=A.w;
        r[xr][4]=B.x; r[xr][5]=B.y; r[xr][6]=B.z; r[xr][7]=B.w;
    }

    float* o = out + blk * 16384 + y * 128u + xq * 32u;
#pragma unroll
    for (int j = 0; j < 4; j++) {
        int i0 = 2 * j, i1 = 2 * j + 1;
        asm volatile(
            "st.global.v8.f32 [%0], {%1,%2,%3,%4,%5,%6,%7,%8};"
            :
            : "l"(o + j * 8),
              "f"(r[0][i0]), "f"(r[1][i0]), "f"(r[2][i0]), "f"(r[3][i0]),
              "f"(r[0][i1]), "f"(r[1][i1]), "f"(r[2][i1]), "f"(r[3][i1])
            : "memory");
    }
}

extern "C" void kernel_launch(void* const* d_in, const int* in_sizes, int n_in,
                              void* d_out, int out_size)
{
    const float* in = (const float*)d_in[0];
    float* out = (float*)d_out;

    cudaFuncSetAttribute(scale_transfer_stage_kernel,
                         cudaFuncAttributeMaxDynamicSharedMemorySize, SMEM_BYTES);

    // 4096 (b,c) blocks, one CTA each
    scale_transfer_stage_kernel<<<4096, 512, SMEM_BYTES>>>(in, out);
}

// round 8
// speedup vs baseline: 1.2045x; 1.2045x over previous
#include <cuda_runtime.h>
#include <cstdint>

// Depth-to-space r=4, x-major channel ordering:
//   out[b, c, y, x] = in[b, c*16 + 4*(x%4) + (y%4), y/4, x/4]
// in : (16, 4096, 32, 32) fp32  -> 256 MB
// out: (16, 256, 128, 128) fp32 -> 256 MB
//
// Champion configuration (round 2), confirmed across 5 counter-experiments:
//  - 256-bit v8.f32 loads/stores: every access is a full 32B sector
//  - warp writes 8 consecutive output rows dense (4KB contiguous per
//    store instruction group); reads are 8x128B chunks per instruction
//  - no cache hints (evict_first measured -4..-7us), natural regs/occupancy
//    (reg caps, 2x MLP, smem/TMA staging all measured neutral or negative)
// Sits at the mixed read/write HBM ceiling: ~6.15 TB/s (77.7% of spec).

__global__ void __launch_bounds__(256) scale_transfer_v8_kernel(
    const float* __restrict__ in, float* __restrict__ out)
{
    unsigned tid = blockIdx.x * blockDim.x + threadIdx.x;
    // tid layout: b[4] c[8] y[7] xq8[2]  -> 16*256*128*4 = 2,097,152 threads
    unsigned xq = tid & 3;            // 8-float group within 32-float input row
    unsigned y  = (tid >> 2) & 127;
    unsigned c  = (tid >> 9) & 255;
    unsigned b  = tid >> 17;

    unsigned yr = y & 3;
    unsigned yb = y >> 2;

    // input float index; channel stride for xr is 4 channels = 4096 floats
    const float* p =
        in + (((b * 4096u + c * 16u + yr) * 32u + yb) * 32u + xq * 8u);

    float r[4][8];
#pragma unroll
    for (int xr = 0; xr < 4; xr++) {
        const float* q = p + xr * 4096;
        asm volatile(
            "ld.global.nc.v8.f32 {%0,%1,%2,%3,%4,%5,%6,%7}, [%8];"
            : "=f"(r[xr][0]), "=f"(r[xr][1]), "=f"(r[xr][2]), "=f"(r[xr][3]),
              "=f"(r[xr][4]), "=f"(r[xr][5]), "=f"(r[xr][6]), "=f"(r[xr][7])
            : "l"(q));
    }

    // output: 32 consecutive floats (x = xq*32 .. xq*32+31) of row (b,c,y)
    float* o = out + (((b * 256u + c) * 128u + y) * 128u + xq * 32u);

#pragma unroll
    for (int j = 0; j < 4; j++) {
        // out local x = 4*i + xr, group j covers i = 2j, 2j+1
        int i0 = 2 * j, i1 = 2 * j + 1;
        asm volatile(
            "st.global.v8.f32 [%0], {%1,%2,%3,%4,%5,%6,%7,%8};"
            :
            : "l"(o + j * 8),
              "f"(r[0][i0]), "f"(r[1][i0]), "f"(r[2][i0]), "f"(r[3][i0]),
              "f"(r[0][i1]), "f"(r[1][i1]), "f"(r[2][i1]), "f"(r[3][i1])
            : "memory");
    }
}

extern "C" void kernel_launch(void* const* d_in, const int* in_sizes, int n_in,
                              void* d_out, int out_size)
{
    const float* in = (const float*)d_in[0];
    float* out = (float*)d_out;

    const int total_threads = 16 * 256 * 128 * 4;  // 2,097,152
    const int block = 256;
    const int grid = total_threads / block;        // 8192

    scale_transfer_v8_kernel<<<grid, block>>>(in, out);
}